// round 4
// baseline (speedup 1.0000x reference)
#include <cuda_runtime.h>
#include <cstdint>

// GatingFeatureExtractor: p[B, E=8, C=1000] fp32 -> feats[B, E*C + 3E + 5] fp32.
// Fully-fused streaming kernel, one CTA per batch row, NO smem data staging:
//   thread t (t<250) owns classes 4t..4t+3. Loop over experts e:
//     LDG.128 (double-buffered) -> stats in registers -> shifted STG.128.
//   Output row misalignment h=(4-b%4)&3 fixed via shfl_down from lane+1
//   (warp-boundary lanes reload the neighbor 16B from gmem/L1).
//   Tiny smem only for cross-warp reductions.

#define EPS_F 1e-8f

constexpr int E = 8;
constexpr int C = 1000;
constexpr int C4 = C / 4;                  // 250
constexpr int EC = E * C;                  // 8000
constexpr int OUTW = EC + 3 * E + 5;       // 8029
constexpr int NT = 256;
constexpr int NW = NT / 32;

__global__ __launch_bounds__(NT, 5)
void gating_feats_kernel(const float* __restrict__ pin, float* __restrict__ out)
{
    __shared__ float sh_m1[E][NW];
    __shared__ float sh_m2[E][NW];
    __shared__ int   sh_i1[E][NW];
    __shared__ float sh_red[NW][11];       // plogp[8], cross, mixent, var

    const int b    = blockIdx.x;
    const int tid  = threadIdx.x;
    const int wid  = tid >> 5;
    const int lane = tid & 31;
    const int t    = tid;
    const bool act = (t < C4);

    const float* __restrict__ pr = pin + (size_t)b * EC;
    float* __restrict__ orow = out + (size_t)b * OUTW;
    // (b*OUTW)%4 == b%4 since OUTW%4==1; dst float4 frame starts at h.
    const int h = (4 - (b & 3)) & 3;

    float pre[4] = {0.f,0.f,0.f,0.f};
    float sum[4] = {0.f,0.f,0.f,0.f};
    float ssq[4] = {0.f,0.f,0.f,0.f};
    float plogp[E];
    float s_cross = 0.f;

    float4 v = make_float4(0.f,0.f,0.f,0.f);
    if (act) v = *reinterpret_cast<const float4*>(pr + 4 * t);

#pragma unroll
    for (int e = 0; e < E; e++) {
        // double-buffer: issue next expert's load before consuming v
        float4 vn = make_float4(0.f,0.f,0.f,0.f);
        if (e + 1 < E && act)
            vn = *reinterpret_cast<const float4*>(pr + (e + 1) * C + 4 * t);

        float vv[4] = {v.x, v.y, v.z, v.w};
        float pe = 0.f, m1 = -1.f, m2 = -1.f;
        int i1 = 0x7fffffff;
#pragma unroll
        for (int i = 0; i < 4; i++) {
            float f = vv[i];
            float lg = __logf(f + EPS_F);
            pe = fmaf(f, lg, pe);
            s_cross = fmaf(lg, pre[i], s_cross);   // sum_{i<j} p_i * logp_j
            pre[i] += f;
            sum[i] += f;
            ssq[i] = fmaf(f, f, ssq[i]);
            if (act) {
                if (f > m1) { m2 = m1; m1 = f; i1 = 4 * t + i; }
                else        { m2 = fmaxf(m2, f); }
            }
        }
        plogp[e] = pe;

        // warp-level top-2 merge for this expert
#pragma unroll
        for (int off = 16; off; off >>= 1) {
            float o1 = __shfl_xor_sync(0xffffffffu, m1, off);
            float o2 = __shfl_xor_sync(0xffffffffu, m2, off);
            int   oi = __shfl_xor_sync(0xffffffffu, i1, off);
            if (o1 > m1 || (o1 == m1 && oi < i1)) {
                m2 = fmaxf(m1, o2); m1 = o1; i1 = oi;
            } else {
                m2 = fmaxf(m2, o1);
            }
        }
        if (lane == 0) { sh_m1[e][wid] = m1; sh_m2[e][wid] = m2; sh_i1[e][wid] = i1; }

        // ---- shifted aligned store of this expert's 4 classes ----
        if (h == 0) {
            if (act)
                *reinterpret_cast<float4*>(orow + e * C + 4 * t) = v;
        } else {
            float4 w;
            w.x = __shfl_down_sync(0xffffffffu, v.x, 1);
            w.y = __shfl_down_sync(0xffffffffu, v.y, 1);
            w.z = __shfl_down_sync(0xffffffffu, v.z, 1);
            w.w = __shfl_down_sync(0xffffffffu, v.w, 1);
            if (act) {
                if (lane == 31 && t < C4 - 1)
                    w = *reinterpret_cast<const float4*>(pr + e * C + 4 * (t + 1));
                if (t == C4 - 1 && e + 1 < E)
                    w = *reinterpret_cast<const float4*>(pr + (e + 1) * C);
                if (!(t == C4 - 1 && e == E - 1)) {
                    const int j = e * C4 + t;
                    float4 o;
                    if (h == 1)      { o.x = v.y; o.y = v.z; o.z = v.w; o.w = w.x; }
                    else if (h == 2) { o.x = v.z; o.y = v.w; o.z = w.x; o.w = w.y; }
                    else             { o.x = v.w; o.y = w.x; o.z = w.y; o.w = w.z; }
                    *reinterpret_cast<float4*>(orow + h + 4 * j) = o;
                }
                if (e == 0 && t == 0) {
                    for (int i = 0; i < h; i++) orow[i] = vv[i];           // head
                }
                if (e == E - 1 && t == C4 - 1) {
                    for (int i = 0; i < 4 - h; i++)
                        orow[EC - 4 + h + i] = vv[h + i];                  // tail
                }
            }
        }
        v = vn;
    }

    // ---- finalize scalar accumulators, warp reduce, stage to smem ----
    float s_mixent = 0.f, s_var = 0.f;
#pragma unroll
    for (int i = 0; i < 4; i++) {
        float m = sum[i] * (1.0f / E);
        s_mixent = fmaf(-m, __logf(m + EPS_F), s_mixent);
        s_var = fmaf(ssq[i] - (float)E * m * m, 1.0f / (float)(E - 1), s_var);
    }
    float r[11];
#pragma unroll
    for (int e = 0; e < E; e++) r[e] = plogp[e];
    r[8] = s_cross; r[9] = s_mixent; r[10] = s_var;
#pragma unroll
    for (int off = 16; off; off >>= 1)
#pragma unroll
        for (int k = 0; k < 11; k++)
            r[k] += __shfl_xor_sync(0xffffffffu, r[k], off);
    if (lane == 0)
#pragma unroll
        for (int k = 0; k < 11; k++) sh_red[wid][k] = r[k];

    __syncthreads();

    // ---- thread 0: the 29 stat columns ----
    if (tid == 0) {
        float acc[11];
#pragma unroll
        for (int k = 0; k < 11; k++) acc[k] = 0.f;
        for (int w = 0; w < NW; w++)
#pragma unroll
            for (int k = 0; k < 11; k++) acc[k] += sh_red[w][k];

        float sum_pl = 0.f, wsum = 0.f;
        int args[E];
#pragma unroll
        for (int e = 0; e < E; e++) {
            float m1 = sh_m1[e][0], m2 = sh_m2[e][0];
            int i1 = sh_i1[e][0];
            for (int w = 1; w < NW; w++) {
                float o1 = sh_m1[e][w], o2 = sh_m2[e][w];
                int oi = sh_i1[e][w];
                if (o1 > m1 || (o1 == m1 && oi < i1)) {
                    m2 = fmaxf(m1, o2); m1 = o1; i1 = oi;
                } else {
                    m2 = fmaxf(m2, o1);
                }
            }
            float pl = acc[e];
            orow[EC + e]         = -pl;          // expert_entropy
            orow[EC + E + e]     = m1;           // expert_confidence
            orow[EC + 2 * E + e] = m1 - m2;      // expert_margin
            sum_pl += pl;
            wsum = fmaf(pl, (float)(E - 1 - e), wsum);
            args[e] = i1;
        }

        // disagreement: sort 8 argmax indices, count unique
        for (int i = 1; i < E; i++) {
            int key = args[i]; int j = i - 1;
            while (j >= 0 && args[j] > key) { args[j + 1] = args[j]; j--; }
            args[j + 1] = key;
        }
        int nuniq = 1;
        for (int i = 1; i < E; i++) nuniq += (args[i] != args[i - 1]) ? 1 : 0;

        const int n_pairs = E * (E - 1) / 2;
        orow[EC + 3 * E + 0] = (float)(nuniq - 1) / (float)(E - 1);  // disagreement_ratio
        orow[EC + 3 * E + 1] = (wsum - acc[8]) / (float)n_pairs;     // mean_pairwise_kl
        orow[EC + 3 * E + 2] = acc[9];                               // mixture_entropy
        orow[EC + 3 * E + 3] = acc[10] / (float)C;                   // post_var
        orow[EC + 3 * E + 4] = acc[9] + sum_pl / (float)E;           // mutual_info
    }
}

extern "C" void kernel_launch(void* const* d_in, const int* in_sizes, int n_in,
                              void* d_out, int out_size)
{
    const float* p = (const float*)d_in[0];
    float* out = (float*)d_out;
    const int B = in_sizes[0] / EC;    // 8192 for this problem's shapes
    gating_feats_kernel<<<B, NT>>>(p, out);
}

// round 5
// speedup vs baseline: 1.3497x; 1.3497x over previous
#include <cuda_runtime.h>
#include <cstdint>

// GatingFeatureExtractor: p[B, E=8, C=1000] fp32 -> feats[B, E*C + 3E + 5] fp32.
// Smem-staged, one CTA per batch row:
//   A: cp.async gmem row -> smem (32KB)
//   B: warp w = expert w: plogp + top2/argmax (float4 LDS), 4-value reduce
//   C+D fused: thread t<250 owns classes 4t..4t+3: per expert load v=sp4[j],
//      w=sp4[j+1]; accumulate prefix-KL cross / mixture / variance AND emit the
//      shift-corrected aligned STG.128 in the same pass.
//   F: thread 0 finalizes the 29 stat columns.

#define EPS_F 1e-8f

constexpr int E = 8;
constexpr int C = 1000;
constexpr int C4 = C / 4;                  // 250
constexpr int EC = E * C;                  // 8000
constexpr int OUTW = EC + 3 * E + 5;       // 8029
constexpr int NT = 256;
constexpr int NW = NT / 32;

__device__ __forceinline__ void cp_async16(uint32_t saddr, const void* gptr) {
    asm volatile("cp.async.cg.shared.global [%0], [%1], 16;\n" ::"r"(saddr), "l"(gptr));
}

__global__ __launch_bounds__(NT, 6)
void gating_feats_kernel(const float* __restrict__ pin, float* __restrict__ out)
{
    __shared__ __align__(16) float sp[EC + 4];     // +4 pad: overlapping w-read
    __shared__ float sh_pl[E], sh_mx1[E], sh_mx2[E];
    __shared__ int   sh_ix1[E];
    __shared__ float sh_scal[NW][3];               // cross, mixent, var

    const int b    = blockIdx.x;
    const int tid  = threadIdx.x;
    const int wid  = tid >> 5;
    const int lane = tid & 31;

    const float* __restrict__ pr = pin + (size_t)b * EC;
    float* __restrict__ orow = out + (size_t)b * OUTW;
    // (b*OUTW)%4 == b%4 since OUTW%4==1; dst float4 frame starts at h.
    const int h = (4 - (b & 3)) & 3;

    // ---------------- Phase A: stage row into smem via cp.async ----------------
    if (tid < C4) {                                 // 250 threads, 8 x 16B each
        uint32_t sbase = (uint32_t)__cvta_generic_to_shared(sp) + 16u * (uint32_t)tid;
#pragma unroll
        for (int e = 0; e < E; e++)
            cp_async16(sbase + (uint32_t)(e * C * 4), pr + e * C + 4 * tid);
    }
    asm volatile("cp.async.commit_group;\n" ::: "memory");
    asm volatile("cp.async.wait_group 0;\n" ::: "memory");
    __syncthreads();

    // -------- Phase B: per-expert plogp + top2/argmax (warp = expert) --------
    {
        const float4* __restrict__ row4 = reinterpret_cast<const float4*>(sp + wid * C);
        float pl = 0.f, m1 = -1.f, m2 = -1.f;
        int i1 = 0;
#pragma unroll
        for (int k = 0; k < 8; k++) {
            int idx = lane + 32 * k;
            if (idx < C4) {
                float4 v = row4[idx];
                float vv[4] = {v.x, v.y, v.z, v.w};
#pragma unroll
                for (int i = 0; i < 4; i++) {
                    float f = vv[i];
                    pl = fmaf(f, __logf(f + EPS_F), pl);
                    if (f > m1) { m2 = m1; m1 = f; i1 = 4 * idx + i; }
                    else        { m2 = fmaxf(m2, f); }
                }
            }
        }
#pragma unroll
        for (int off = 16; off; off >>= 1) {
            pl += __shfl_xor_sync(0xffffffffu, pl, off);
            float o1 = __shfl_xor_sync(0xffffffffu, m1, off);
            float o2 = __shfl_xor_sync(0xffffffffu, m2, off);
            int   oi = __shfl_xor_sync(0xffffffffu, i1, off);
            if (o1 > m1 || (o1 == m1 && oi < i1)) {
                m2 = fmaxf(m1, o2); m1 = o1; i1 = oi;
            } else {
                m2 = fmaxf(m2, o1);
            }
        }
        if (lane == 0) {
            sh_pl[wid] = pl; sh_mx1[wid] = m1; sh_mx2[wid] = m2; sh_ix1[wid] = i1;
        }
    }

    // -------- Phase C+D fused: cross-expert stats + shifted copy --------
    {
        float s_cross = 0.f, s_mixent = 0.f, s_var = 0.f;
        if (tid < C4) {
            const int t = tid;
            float pre[4] = {0.f,0.f,0.f,0.f};
            float ssq[4] = {0.f,0.f,0.f,0.f};
            const float4* __restrict__ sp4 = reinterpret_cast<const float4*>(sp);
#pragma unroll
            for (int e = 0; e < E; e++) {
                const int j = e * C4 + t;
                float4 v = sp4[j];
                float vv[4] = {v.x, v.y, v.z, v.w};
#pragma unroll
                for (int i = 0; i < 4; i++) {
                    float f = vv[i];
                    float lg = __logf(f + EPS_F);
                    s_cross = fmaf(lg, pre[i], s_cross);  // sum_{i<j} p_i * logp_j
                    pre[i] += f;
                    ssq[i] = fmaf(f, f, ssq[i]);
                }
                // shifted aligned store of this quad
                if (h == 0) {
                    *reinterpret_cast<float4*>(orow + 4 * j) = v;
                } else {
                    float4 w = sp4[j + 1];                 // padded overlap read
                    if (j < EC / 4 - 1) {                  // last quad -> tail scalars
                        float4 o;
                        if (h == 1)      { o.x = v.y; o.y = v.z; o.z = v.w; o.w = w.x; }
                        else if (h == 2) { o.x = v.z; o.y = v.w; o.z = w.x; o.w = w.y; }
                        else             { o.x = v.w; o.y = w.x; o.z = w.y; o.w = w.z; }
                        *reinterpret_cast<float4*>(orow + h + 4 * j) = o;
                    } else {
#pragma unroll
                        for (int i = 0; i < 4; i++)        // tail: last 4-h floats
                            if (i >= h) orow[EC - 4 + i] = vv[i];
                    }
                    if (e == 0 && t == 0)
                        for (int i = 0; i < h; i++) orow[i] = vv[i];   // head
                }
            }
            // pre[] now holds the full expert sum per class (mixture*E)
#pragma unroll
            for (int i = 0; i < 4; i++) {
                float m = pre[i] * (1.0f / E);
                s_mixent = fmaf(-m, __logf(m + EPS_F), s_mixent);
                s_var = fmaf(ssq[i] - (float)E * m * m, 1.0f / (float)(E - 1), s_var);
            }
        }
#pragma unroll
        for (int off = 16; off; off >>= 1) {
            s_cross  += __shfl_xor_sync(0xffffffffu, s_cross, off);
            s_mixent += __shfl_xor_sync(0xffffffffu, s_mixent, off);
            s_var    += __shfl_xor_sync(0xffffffffu, s_var, off);
        }
        if (lane == 0) {
            sh_scal[wid][0] = s_cross; sh_scal[wid][1] = s_mixent; sh_scal[wid][2] = s_var;
        }
    }

    __syncthreads();

    // ---------------- Finalize: 29 stat columns ----------------
    if (tid == 0) {
        float sum_pl = 0.f, wsum = 0.f;
        int args[E];
#pragma unroll
        for (int e = 0; e < E; e++) {
            float pl = sh_pl[e];
            orow[EC + e]         = -pl;                      // expert_entropy
            orow[EC + E + e]     = sh_mx1[e];                // expert_confidence
            orow[EC + 2 * E + e] = sh_mx1[e] - sh_mx2[e];    // expert_margin
            sum_pl += pl;
            wsum = fmaf(pl, (float)(E - 1 - e), wsum);
            args[e] = sh_ix1[e];
        }

        // disagreement: sort 8 argmax indices, count unique
        for (int i = 1; i < E; i++) {
            int key = args[i]; int j = i - 1;
            while (j >= 0 && args[j] > key) { args[j + 1] = args[j]; j--; }
            args[j + 1] = key;
        }
        int nuniq = 1;
        for (int i = 1; i < E; i++) nuniq += (args[i] != args[i - 1]) ? 1 : 0;

        float Sx = 0.f, mixent = 0.f, varsum = 0.f;
        for (int w = 0; w < NW; w++) {
            Sx += sh_scal[w][0]; mixent += sh_scal[w][1]; varsum += sh_scal[w][2];
        }
        const int n_pairs = E * (E - 1) / 2;
        orow[EC + 3 * E + 0] = (float)(nuniq - 1) / (float)(E - 1);  // disagreement_ratio
        orow[EC + 3 * E + 1] = (wsum - Sx) / (float)n_pairs;         // mean_pairwise_kl
        orow[EC + 3 * E + 2] = mixent;                               // mixture_entropy
        orow[EC + 3 * E + 3] = varsum / (float)C;                    // post_var
        orow[EC + 3 * E + 4] = mixent + sum_pl / (float)E;           // mutual_info
    }
}

extern "C" void kernel_launch(void* const* d_in, const int* in_sizes, int n_in,
                              void* d_out, int out_size)
{
    const float* p = (const float*)d_in[0];
    float* out = (float*)d_out;
    const int B = in_sizes[0] / EC;    // 8192 for this problem's shapes
    gating_feats_kernel<<<B, NT>>>(p, out);
}